// round 16
// baseline (speedup 1.0000x reference)
#include <cuda_runtime.h>
#include <cuda_fp16.h>
#include <math.h>
#include <stdint.h>

#define BATCH 4
#define NQ 2048
#define NM 2048
#define DIM 1024
#define HEADS 8
#define DHEAD 64
#define INNER 512
#define ROWS (BATCH * NQ)

// ---------------- scratch ----------------
__device__ __align__(16) uint32_t g_xnh  [ROWS * DIM / 2];
__device__ __align__(16) uint32_t g_ctxh [ROWS * DIM / 2];
__device__ __align__(16) float    g_q    [ROWS * INNER];
__device__ __align__(16) uint32_t g_kf   [32 * 32 * 2048];
__device__ __align__(16) uint32_t g_vf   [32 * 32 * 2048];
__device__ __align__(16) uint32_t g_attnh[ROWS * INNER / 2];
__device__ __align__(16) float    g_out2 [ROWS * DIM];
__device__ __align__(16) __half   g_wqTh [INNER * DIM];
__device__ __align__(16) __half   g_wkvTh[2 * INNER * DIM];
__device__ __align__(16) __half   g_woutTh[DIM * INNER];

// ---------------- helpers ----------------
__device__ __forceinline__ uint32_t pack_f16x2(float x, float y) {
    __half2 h = __floats2half2_rn(x, y);
    return *(uint32_t*)&h;
}
__device__ __forceinline__ uint32_t smem_u32(const void* p) {
    uint32_t a;
    asm("{ .reg .u64 t; cvta.to.shared.u64 t, %1; cvt.u32.u64 %0, t; }" : "=r"(a) : "l"(p));
    return a;
}
#define CP_ASYNC16(saddr, gptr) \
    asm volatile("cp.async.cg.shared.global [%0], [%1], 16;" :: "r"(saddr), "l"(gptr))
#define CP_COMMIT() asm volatile("cp.async.commit_group;" ::: "memory")
#define CP_WAIT1()  asm volatile("cp.async.wait_group 1;" ::: "memory")
#define CP_WAIT0()  asm volatile("cp.async.wait_group 0;" ::: "memory")

#define MMA_F16(d, a, b0, b1) \
    asm volatile("mma.sync.aligned.m16n8k16.row.col.f32.f16.f16.f32 " \
        "{%0,%1,%2,%3}, {%4,%5,%6,%7}, {%8,%9}, {%0,%1,%2,%3};" \
        : "+f"((d)[0]), "+f"((d)[1]), "+f"((d)[2]), "+f"((d)[3]) \
        : "r"((a)[0]), "r"((a)[1]), "r"((a)[2]), "r"((a)[3]), "r"(b0), "r"(b1))

// ---------------- LayerNorm (outHalf=1: fp16 pair output) ----------------
__global__ __launch_bounds__(256) void ln1024_kernel(
    const float* __restrict__ x, const float* __restrict__ gamma,
    void* __restrict__ out, int outHalf)
{
    const int row = blockIdx.x, tid = threadIdx.x;
    const float4 v = reinterpret_cast<const float4*>(x + (size_t)row * 1024)[tid];
    float s = v.x + v.y + v.z + v.w;
    float sq = v.x*v.x + v.y*v.y + v.z*v.z + v.w*v.w;
    #pragma unroll
    for (int o = 16; o > 0; o >>= 1) {
        s  += __shfl_xor_sync(0xffffffffu, s, o);
        sq += __shfl_xor_sync(0xffffffffu, sq, o);
    }
    __shared__ float ss[8], sqq[8];
    if ((tid & 31) == 0) { ss[tid >> 5] = s; sqq[tid >> 5] = sq; }
    __syncthreads();
    float tot = 0.f, totq = 0.f;
    #pragma unroll
    for (int i = 0; i < 8; i++) { tot += ss[i]; totq += sqq[i]; }
    const float mu = tot * (1.f/1024.f);
    const float inv = rsqrtf(totq * (1.f/1024.f) - mu*mu + 1e-5f);
    const float4 g = reinterpret_cast<const float4*>(gamma)[tid];
    float4 o;
    o.x = (v.x - mu)*inv*g.x; o.y = (v.y - mu)*inv*g.y;
    o.z = (v.z - mu)*inv*g.z; o.w = (v.w - mu)*inv*g.w;
    if (outHalf) {
        uint2 p = make_uint2(pack_f16x2(o.x, o.y), pack_f16x2(o.z, o.w));
        reinterpret_cast<uint2*>((uint32_t*)out + (size_t)row * 512)[tid] = p;
    } else {
        reinterpret_cast<float4*>((float*)out + (size_t)row * 1024)[tid] = o;
    }
}

// ---------------- merged prep: 3 weight transposes + context->fp16 ----------------
__global__ __launch_bounds__(256) void prep_kernel(
    const float* __restrict__ w_q, const float* __restrict__ w_kv,
    const float* __restrict__ w_out, const float* __restrict__ ctx,
    __half* __restrict__ wqT, __half* __restrict__ wkvT,
    __half* __restrict__ woutT, uint32_t* __restrict__ ctxh)
{
    const int bid = blockIdx.x;
    if (bid >= 2048) {
        const int i = (bid - 2048) * 256 + threadIdx.x;
        float4 v = reinterpret_cast<const float4*>(ctx)[i];
        reinterpret_cast<uint2*>(ctxh)[i] =
            make_uint2(pack_f16x2(v.x, v.y), pack_f16x2(v.z, v.w));
        return;
    }
    const float* w; __half* wT; int K, N, t;
    if (bid < 512)       { w = w_q;   wT = wqT;   K = 1024; N = 512;  t = bid; }
    else if (bid < 1536) { w = w_kv;  wT = wkvT;  K = 1024; N = 1024; t = bid - 512; }
    else                 { w = w_out; wT = woutT; K = 512;  N = 1024; t = bid - 1536; }
    const int nx = N / 32;
    const int n0 = (t % nx) * 32, k0 = (t / nx) * 32;
    __shared__ float tt[32][33];
    const int tx = threadIdx.x & 31, ty = threadIdx.x >> 5;
    #pragma unroll
    for (int i = ty; i < 32; i += 8) tt[i][tx] = w[(size_t)(k0+i)*N + n0 + tx];
    __syncthreads();
    #pragma unroll
    for (int i = ty; i < 32; i += 8) wT[(size_t)(n0+i)*K + k0 + tx] = __float2half(tt[tx][i]);
}

// ---------------- FP16 GEMM: 256 thr, CTA tile 256x128, warp 64x64, 3-stage ring ----------------
#define HSTRIDE 40                                  // halfs per row (32 data + 8 pad)
#define ATILE_H (256 * HSTRIDE)                     // 10240 halfs = 20480 B
#define BTILE_H (128 * HSTRIDE)                     // 5120 halfs = 10240 B
#define HSTAGE  (ATILE_H + BTILE_H)                 // 15360 halfs = 30720 B
#define GEMM_SMEM_BYTES (3 * HSTAGE * 2)            // 92160

__global__ __launch_bounds__(256, 1) void hgemm_kernel(
    const __half* __restrict__ A, const __half* __restrict__ BT,
    float* __restrict__ C, uint32_t* __restrict__ Cv,
    int N, int K, int mode,
    const __half* __restrict__ A2, const __half* __restrict__ BT2,
    float* __restrict__ C2, int fuseQ)
{
    extern __shared__ __half smh[];
    float* smf = (float*)smh;
    const uint32_t smb = smem_u32(smh);
    const int tid = threadIdx.x, wid = tid >> 5, lane = tid & 31;
    const int wm = wid & 3, wn = wid >> 2;          // warp grid 4(m) x 2(n)
    const int m0 = blockIdx.y * 256;
    int n0 = blockIdx.x * 128;
    if (fuseQ) {
        if (blockIdx.x < 4) { A = A2; BT = BT2; C = C2; N = 512; mode = 0; }
        else                { n0 = (blockIdx.x - 4) * 128; }
    }
    const __half* Abase = A + (size_t)m0 * K;
    const __half* Bbase = BT + (size_t)n0 * K;

    auto load_stage = [&](int s, int kt) {
        const uint32_t sA = smb + (uint32_t)s * HSTAGE * 2;
        const uint32_t sB = sA + ATILE_H * 2;
        const __half* Ab = Abase + (size_t)kt * 32;
        const __half* Bb = Bbase + (size_t)kt * 32;
        #pragma unroll
        for (int j = 0; j < 6; j++) {
            const int idx = tid + 256 * j;          // 0..1535 chunks of 16B
            if (idx < 1024) {
                const int row = idx >> 2, ch = idx & 3;
                CP_ASYNC16(sA + (uint32_t)(row * 80 + ch * 16),
                           Ab + (size_t)row * K + ch * 8);
            } else {
                const int i2 = idx - 1024;
                const int row = i2 >> 2, ch = i2 & 3;
                CP_ASYNC16(sB + (uint32_t)(row * 80 + ch * 16),
                           Bb + (size_t)row * K + ch * 8);
            }
        }
        CP_COMMIT();
    };

    float acc[4][8][4];
    #pragma unroll
    for (int mi = 0; mi < 4; mi++)
        #pragma unroll
        for (int ni = 0; ni < 8; ni++)
            #pragma unroll
            for (int r = 0; r < 4; r++) acc[mi][ni][r] = 0.f;

    const int KT = K / 32;
    load_stage(0, 0); load_stage(1, 1);
    const int g = lane >> 2, c = lane & 3;

    int rd = 0, ld = 2;
    for (int kt = 0; kt < KT; kt++) {
        if (kt < KT - 1) CP_WAIT1(); else CP_WAIT0();
        __syncthreads();
        const __half* As = smh + (size_t)rd * HSTAGE;
        const __half* Bs = As + ATILE_H;
        #pragma unroll
        for (int t = 0; t < 2; t++) {
            const int kc = 16*t + 2*c;
            uint32_t af[4][4], bf[8][2];
            #pragma unroll
            for (int mi = 0; mi < 4; mi++) {
                const int r = wm*64 + mi*16 + g;
                af[mi][0] = *(const uint32_t*)&As[r*HSTRIDE + kc];
                af[mi][1] = *(const uint32_t*)&As[(r+8)*HSTRIDE + kc];
                af[mi][2] = *(const uint32_t*)&As[r*HSTRIDE + kc + 8];
                af[mi][3] = *(const uint32_t*)&As[(r+8)*HSTRIDE + kc + 8];
            }
            #pragma unroll
            for (int ni = 0; ni < 8; ni++) {
                const int nr = wn*64 + ni*8 + g;
                bf[ni][0] = *(const uint32_t*)&Bs[nr*HSTRIDE + kc];
                bf[ni][1] = *(const uint32_t*)&Bs[nr*HSTRIDE + kc + 8];
            }
            #pragma unroll
            for (int mi = 0; mi < 4; mi++)
                #pragma unroll
                for (int ni = 0; ni < 8; ni++)
                    MMA_F16(acc[mi][ni], af[mi], bf[ni][0], bf[ni][1]);
        }
        if (kt + 2 < KT) load_stage(ld, kt + 2);
        rd = (rd == 2) ? 0 : rd + 1;
        ld = (ld == 2) ? 0 : ld + 1;
    }

    if (mode == 0) {
        #pragma unroll
        for (int mi = 0; mi < 4; mi++) {
            const int row = m0 + wm*64 + mi*16 + g;
            #pragma unroll
            for (int ni = 0; ni < 8; ni++) {
                const int col = n0 + wn*64 + ni*8 + c*2;
                *reinterpret_cast<float2*>(C + (size_t)row*N + col) =
                    make_float2(acc[mi][ni][0], acc[mi][ni][1]);
                *reinterpret_cast<float2*>(C + (size_t)(row+8)*N + col) =
                    make_float2(acc[mi][ni][2], acc[mi][ni][3]);
            }
        }
    } else if (n0 < 512) {
        // K frag-major single-limb fp16
        uint32_t* Kf = (uint32_t*)C;
        auto kstore = [&](int row, int col, uint32_t hp) {
            const int b_ = row >> 11, kt = (row & 2047) >> 6, j = (row & 63) >> 3, gk = row & 7;
            const int h_ = col >> 6, dd = col & 63, t = dd >> 4, ck = (dd & 7) >> 1, rg = (dd >> 3) & 1;
            const size_t u = ((((size_t)(b_*8 + h_)*32 + kt)*8 + j)*4 + t)*64 + (4*gk + ck)*2;
            Kf[u + rg] = hp;
        };
        #pragma unroll
        for (int mi = 0; mi < 4; mi++) {
            const int row = m0 + wm*64 + mi*16 + g;
            #pragma unroll
            for (int ni = 0; ni < 8; ni++) {
                const int col = n0 + wn*64 + ni*8 + 2*c;
                kstore(row,     col, pack_f16x2(acc[mi][ni][0], acc[mi][ni][1]));
                kstore(row + 8, col, pack_f16x2(acc[mi][ni][2], acc[mi][ni][3]));
            }
        }
    } else {
        // V frag-major: two 128-row staging passes (smem [128][132] fp32)
        const int n0v = n0 - 512;
        uint32_t* Vf = Cv;
        const int b_ = m0 >> 11;
        #pragma unroll
        for (int p = 0; p < 2; p++) {
            __syncthreads();
            if ((wm >> 1) == p) {
                const int wml = wm & 1;
                #pragma unroll
                for (int mi = 0; mi < 4; mi++) {
                    const int r0 = wml*64 + mi*16 + g;
                    #pragma unroll
                    for (int ni = 0; ni < 8; ni++) {
                        const int cc = wn*64 + ni*8 + 2*c;
                        *reinterpret_cast<float2*>(&smf[r0*132 + cc]) =
                            make_float2(acc[mi][ni][0], acc[mi][ni][1]);
                        *reinterpret_cast<float2*>(&smf[(r0+8)*132 + cc]) =
                            make_float2(acc[mi][ni][2], acc[mi][ni][3]);
                    }
                }
            }
            __syncthreads();
            #pragma unroll
            for (int it = 0; it < 32; it++) {
                const int idx = tid + 256*it;           // n(128 d) x mp(64 kv-pairs)
                const int n = idx >> 6, mp = idx & 63;
                const uint32_t hp = pack_f16x2(smf[(2*mp)*132 + n], smf[(2*mp+1)*132 + n]);
                const int kvl = (m0 & 2047) + p*128 + 2*mp;
                const int kt = kvl >> 6, kvp = kvl & 63;
                const int t = kvp >> 4, cv = (kvp & 7) >> 1, rg = (kvp >> 3) & 1;
                const int hd = n0v + n, h_ = hd >> 6, dd = hd & 63, j = dd >> 3, gv = dd & 7;
                const size_t u = ((((size_t)(b_*8 + h_)*32 + kt)*8 + j)*4 + t)*64 + (4*gv + cv)*2;
                Vf[u + rg] = hp;
            }
        }
    }
}

// ---------------- Flash: 256 thr, BQ=256, warp=32 q-rows, max-free softmax ----------------
#define FLASH_SMEM (69632 + 512 + 512)
#define QSCALE (0.125f * 1.44269504088896f)

__global__ __launch_bounds__(256, 1) void flash_f16_kernel(
    const float* __restrict__ Q,
    const uint32_t* __restrict__ Kf, const uint32_t* __restrict__ Vf,
    const float* __restrict__ NKV, uint32_t* __restrict__ Oh)
{
    extern __shared__ float smf[];
    const uint32_t smb = smem_u32(smf);
    const int tid = threadIdx.x, lane = tid & 31, w = tid >> 5;   // 8 warps
    const int g = lane >> 2, c = lane & 3;
    const int bh = blockIdx.y, b = bh >> 3, h = bh & 7;
    const int q0 = blockIdx.x * 256;
    float* nk = smf + 17408;
    if (tid < 128) nk[tid] = NKV[tid];

    // Q staging [256][68] fp32 (covers the 3x16KB ring; freed before ring use)
    const float* qbase = Q + ((size_t)(b*NQ + q0))*INNER + h*DHEAD;
    #pragma unroll
    for (int rl = 0; rl < 16; rl++) {
        const int idx = tid + 256*rl;
        const int r = idx >> 4, c4 = idx & 15;
        CP_ASYNC16(smb + (uint32_t)(r*68 + c4*4)*4, qbase + (size_t)r*INNER + c4*4);
    }
    CP_COMMIT(); CP_WAIT0();
    __syncthreads();

    uint32_t qh[2][4][4];
    float sn[2][2] = {{0.f,0.f},{0.f,0.f}};
    #pragma unroll
    for (int mt = 0; mt < 2; mt++) {
        const int rb = 32*w + 16*mt;
        #pragma unroll
        for (int t = 0; t < 4; t++) {
            const int col = 16*t + 2*c;
            float2 f0 = *(float2*)&smf[(rb + g)*68 + col];
            float2 f1 = *(float2*)&smf[(rb + 8 + g)*68 + col];
            float2 f2 = *(float2*)&smf[(rb + g)*68 + col + 8];
            float2 f3 = *(float2*)&smf[(rb + 8 + g)*68 + col + 8];
            f0.x *= QSCALE; f0.y *= QSCALE; f1.x *= QSCALE; f1.y *= QSCALE;
            f2.x *= QSCALE; f2.y *= QSCALE; f3.x *= QSCALE; f3.y *= QSCALE;
            sn[mt][0] += f0.x*nk[col] + f0.y*nk[col+1] + f2.x*nk[col+8] + f2.y*nk[col+9];
            sn[mt][1] += f1.x*nk[col] + f1.y*nk[col+1] + f3.x*nk[col+8] + f3.y*nk[col+9];
            qh[mt][t][0] = pack_f16x2(f0.x, f0.y);
            qh[mt][t][1] = pack_f16x2(f1.x, f1.y);
            qh[mt][t][2] = pack_f16x2(f2.x, f2.y);
            qh[mt][t][3] = pack_f16x2(f3.x, f3.y);
        }
    }
    float lv[2][2], oacc[2][8][4];
    #pragma unroll
    for (int mt = 0; mt < 2; mt++)
        #pragma unroll
        for (int hb = 0; hb < 2; hb++) {
            float s = sn[mt][hb];
            s += __shfl_xor_sync(0xffffffffu, s, 1);
            s += __shfl_xor_sync(0xffffffffu, s, 2);
            sn[mt][hb] = exp2f(s);                    // null weight
            lv[mt][hb] = (c == 0) ? sn[mt][hb] : 0.f;
        }
    #pragma unroll
    for (int mt = 0; mt < 2; mt++)
        #pragma unroll
        for (int j = 0; j < 8; j++) {
            const float nv0 = nk[64 + 8*j + 2*c], nv1 = nk[64 + 8*j + 2*c + 1];
            oacc[mt][j][0] = nv0 * sn[mt][0]; oacc[mt][j][1] = nv1 * sn[mt][0];
            oacc[mt][j][2] = nv0 * sn[mt][1]; oacc[mt][j][3] = nv1 * sn[mt][1];
        }
    __syncthreads();

    const uint32_t* kfb = Kf + (size_t)bh * 32 * 2048;
    const uint32_t* vfb = Vf + (size_t)bh * 32 * 2048;

    auto load_kv = [&](int st, int kt) {
        const uint32_t base = smb + (uint32_t)st * 16384u;
        const uint32_t* ks = kfb + (size_t)kt * 2048;
        const uint32_t* vs = vfb + (size_t)kt * 2048;
        #pragma unroll
        for (int r = 0; r < 4; r++) {
            const int idx = tid + 256*r;    // 0..1023 chunks of 16B
            if (idx < 512) CP_ASYNC16(base + (uint32_t)idx*16, ks + idx*4);
            else           CP_ASYNC16(base + (uint32_t)idx*16, vs + (idx-512)*4);
        }
        CP_COMMIT();
    };
    load_kv(0, 0); load_kv(1, 1);

    int rd = 0, ld = 2;
    for (int kt = 0; kt < 32; kt++) {
        if (kt < 31) CP_WAIT1(); else CP_WAIT0();
        __syncthreads();
        const uint2* ks2 = (const uint2*)((const char*)smf + rd*16384);
        const uint2* vs2 = ks2 + 1024;

        // S = Q K^T : each K fragment feeds both m-tiles (2 mma per LDS.64)
        float s[2][8][4];
        #pragma unroll
        for (int j = 0; j < 8; j++) {
            s[0][j][0]=s[0][j][1]=s[0][j][2]=s[0][j][3]=0.f;
            s[1][j][0]=s[1][j][1]=s[1][j][2]=s[1][j][3]=0.f;
            #pragma unroll
            for (int t = 0; t < 4; t++) {
                const uint2 kk = ks2[(j*4 + t)*32 + lane];
                MMA_F16(s[0][j], qh[0][t], kk.x, kk.y);
                MMA_F16(s[1][j], qh[1][t], kk.x, kk.y);
            }
        }

        // P = exp2(s), per-thread l accumulation (max-free)
        uint32_t ph[2][4][4];
        #pragma unroll
        for (int mt = 0; mt < 2; mt++) {
            #pragma unroll
            for (int j = 0; j < 8; j++) {
                s[mt][j][0] = exp2f(s[mt][j][0]); s[mt][j][1] = exp2f(s[mt][j][1]);
                s[mt][j][2] = exp2f(s[mt][j][2]); s[mt][j][3] = exp2f(s[mt][j][3]);
                lv[mt][0] += s[mt][j][0] + s[mt][j][1];
                lv[mt][1] += s[mt][j][2] + s[mt][j][3];
            }
            #pragma unroll
            for (int t = 0; t < 4; t++) {
                ph[mt][t][0] = pack_f16x2(s[mt][2*t][0],   s[mt][2*t][1]);
                ph[mt][t][1] = pack_f16x2(s[mt][2*t][2],   s[mt][2*t][3]);
                ph[mt][t][2] = pack_f16x2(s[mt][2*t+1][0], s[mt][2*t+1][1]);
                ph[mt][t][3] = pack_f16x2(s[mt][2*t+1][2], s[mt][2*t+1][3]);
            }
        }

        if (kt + 2 < 32) load_kv(ld, kt + 2);

        // O += P V : each V fragment feeds both m-tiles
        #pragma unroll
        for (int j = 0; j < 8; j++) {
            #pragma unroll
            for (int t = 0; t < 4; t++) {
                const uint2 vv = vs2[(j*4 + t)*32 + lane];
                MMA_F16(oacc[0][j], ph[0][t], vv.x, vv.y);
                MMA_F16(oacc[1][j], ph[1][t], vv.x, vv.y);
            }
        }
        rd = (rd == 2) ? 0 : rd + 1;
        ld = (ld == 2) ? 0 : ld + 1;
    }

    // final l reduction + store
    #pragma unroll
    for (int mt = 0; mt < 2; mt++) {
        #pragma unroll
        for (int hb = 0; hb < 2; hb++) {
            lv[mt][hb] += __shfl_xor_sync(0xffffffffu, lv[mt][hb], 1);
            lv[mt][hb] += __shfl_xor_sync(0xffffffffu, lv[mt][hb], 2);
        }
        const float inv0 = 1.f / lv[mt][0], inv1 = 1.f / lv[mt][1];
        uint32_t* ob = Oh + ((size_t)(b*NQ + q0 + 32*w + 16*mt))*256 + h*32;
        #pragma unroll
        for (int j = 0; j < 8; j++) {
            ob[(size_t)g*256 + 4*j + c] =
                pack_f16x2(oacc[mt][j][0]*inv0, oacc[mt][j][1]*inv0);
            ob[(size_t)(8+g)*256 + 4*j + c] =
                pack_f16x2(oacc[mt][j][2]*inv1, oacc[mt][j][3]*inv1);
        }
    }
}

// ---------------- launcher ----------------
extern "C" void kernel_launch(void* const* d_in, const int* in_sizes, int n_in,
                              void* d_out, int out_size)
{
    const float* x         = (const float*)d_in[0];
    const float* context   = (const float*)d_in[1];
    const float* gamma     = (const float*)d_in[3];
    const float* w_q       = (const float*)d_in[4];
    const float* w_kv      = (const float*)d_in[5];
    const float* null_kv   = (const float*)d_in[6];
    const float* w_out     = (const float*)d_in[7];
    const float* out_gamma = (const float*)d_in[8];
    float* out = (float*)d_out;

    uint32_t *xnh, *ctxh, *kf, *vf, *attnh;
    float *q, *out2;
    __half *wqTh, *wkvTh, *woutTh;
    cudaGetSymbolAddress((void**)&xnh,    g_xnh);
    cudaGetSymbolAddress((void**)&ctxh,   g_ctxh);
    cudaGetSymbolAddress((void**)&q,      g_q);
    cudaGetSymbolAddress((void**)&kf,     g_kf);
    cudaGetSymbolAddress((void**)&vf,     g_vf);
    cudaGetSymbolAddress((void**)&attnh,  g_attnh);
    cudaGetSymbolAddress((void**)&out2,   g_out2);
    cudaGetSymbolAddress((void**)&wqTh,   g_wqTh);
    cudaGetSymbolAddress((void**)&wkvTh,  g_wkvTh);
    cudaGetSymbolAddress((void**)&woutTh, g_woutTh);

    cudaFuncSetAttribute(hgemm_kernel, cudaFuncAttributeMaxDynamicSharedMemorySize, GEMM_SMEM_BYTES);
    cudaFuncSetAttribute(flash_f16_kernel, cudaFuncAttributeMaxDynamicSharedMemorySize, FLASH_SMEM);

    ln1024_kernel<<<ROWS, 256>>>(x, gamma, xnh, 1);
    prep_kernel<<<2048 + (ROWS * DIM / 4) / 256, 256>>>(
        w_q, w_kv, w_out, context, wqTh, wkvTh, woutTh, ctxh);

    // fused q + kv projections (CTA tile 256x128)
    hgemm_kernel<<<dim3(12, 32), 256, GEMM_SMEM_BYTES>>>(
        (const __half*)ctxh, wkvTh, (float*)kf, vf, 1024, DIM, 3,
        (const __half*)xnh, wqTh, q, 1);
    // attention
    flash_f16_kernel<<<dim3(8, 32), 256, FLASH_SMEM>>>(q, kf, vf, null_kv, attnh);
    // output projection + final LN
    hgemm_kernel<<<dim3(8, 32), 256, GEMM_SMEM_BYTES>>>(
        (const __half*)attnh, woutTh, out2, nullptr, DIM, INNER, 0,
        nullptr, nullptr, nullptr, 0);
    ln1024_kernel<<<ROWS, 256>>>(out2, out_gamma, out, 0);
}